// round 13
// baseline (speedup 1.0000x reference)
#include <cuda_runtime.h>
#include <cuda_bf16.h>
#include <cstdint>

// DotAttentionEluX — math collapses:
//   out[b,h,i,:] = (sum_j ks_j * v_j) / (sum_j ks_j)  for every row i,
//   ks_j = sum_d (elu(k[b,h,j,d]) + 1).  Query cancels entirely.
//
// Model after R4-R12: read 32MB ~5.7us (near ceiling); write 16MB ~7us
// (~2.3TB/s hw cap, mechanism-invariant); all big-footprint overlap schemes
// regressed. R13: proven 512-CTA reader untouched + ONLY 32 writer CTAs
// (one per bh, 6% of slots) that spin on per-bh counters and bulk-write
// 512KB each. Early bh writes overlap the read tail; downside bounded.

static constexpr int B_ = 4, H_ = 8, L_ = 2048, D_ = 64;
static constexpr int BH = B_ * H_;                  // 32
static constexpr int NSPLIT = 16;
static constexpr int ROWS_PER_SPLIT = L_ / NSPLIT;  // 128
static constexpr int WARPS = 8;
static constexpr int NREADER = BH * NSPLIT;         // 512
static constexpr int NWRITER = BH;                  // 32 (one per bh)
static constexpr int NCTA = NREADER + NWRITER;      // 544, all co-resident

__device__ float g_num[BH * NSPLIT * D_];
__device__ float g_den[BH * NSPLIT];
__device__ int   g_cnt[BH];   // reader arrivals per bh; writer resets

__device__ __forceinline__ float elu1(float x) {
    return x > 0.0f ? x + 1.0f : __expf(x);
}

static constexpr int STAGE_ROWS = 128;                    // writer staging
static constexpr int STAGE_BYTES = STAGE_ROWS * D_ * 4;   // 32 KB

struct SmemReader { float4 s_num[WARPS * 2][D_ / 4]; float s_den[WARPS * 2]; };
struct SmemWriter { float4 s_buf[STAGE_ROWS * (D_ / 4)]; float4 s_w4[D_ / 4]; };

__global__ __launch_bounds__(256) void fused_kernel(
    const float* __restrict__ K, const float* __restrict__ V,
    float* __restrict__ out)
{
    __shared__ union U { SmemReader r; SmemWriter w;
                         __device__ U() {} } sm;
    const int t    = threadIdx.x;
    const int warp = t >> 5;
    const int lane = t & 31;
    const int half = lane >> 4;
    const int q    = lane & 15;

    if (blockIdx.x < NREADER) {
        // -------- READER: byte-identical structure to the proven R6 accum --
        const int bh    = blockIdx.x / NSPLIT;
        const int split = blockIdx.x % NSPLIT;

        const size_t base = ((size_t)bh * L_ + split * ROWS_PER_SPLIT
                             + (size_t)warp * 2 + half) * D_ + (size_t)q * 4;
        const float4* __restrict__ Kp = reinterpret_cast<const float4*>(K + base);
        const float4* __restrict__ Vp = reinterpret_cast<const float4*>(V + base);
        constexpr int STRIDE4 = WARPS * 2 * D_ / 4;
        constexpr int NPAIR   = ROWS_PER_SPLIT / (WARPS * 2);   // 8

        float n0 = 0.f, n1 = 0.f, n2 = 0.f, n3 = 0.f, den = 0.f;
        #pragma unroll
        for (int r = 0; r < NPAIR; r++) {
            float4 kk = Kp[(size_t)r * STRIDE4];
            float4 vv = Vp[(size_t)r * STRIDE4];
            float ks = elu1(kk.x) + elu1(kk.y) + elu1(kk.z) + elu1(kk.w);
            #pragma unroll
            for (int o = 8; o; o >>= 1)
                ks += __shfl_xor_sync(0xffffffffu, ks, o);
            n0 += ks * vv.x;  n1 += ks * vv.y;
            n2 += ks * vv.z;  n3 += ks * vv.w;
            if (q == 0) den += ks;
        }

        const int wh = warp * 2 + half;
        sm.r.s_num[wh][q] = make_float4(n0, n1, n2, n3);
        if (q == 0) sm.r.s_den[wh] = den;
        __syncthreads();

        if (t < D_) {
            const float* sn = reinterpret_cast<const float*>(sm.r.s_num);
            float s = 0.0f;
            #pragma unroll
            for (int w = 0; w < WARPS * 2; w++) s += sn[w * D_ + t];
            g_num[(bh * NSPLIT + split) * D_ + t] = s;
        }
        if (t == D_) {
            float s = 0.0f;
            #pragma unroll
            for (int w = 0; w < WARPS * 2; w++) s += sm.r.s_den[w];
            g_den[bh * NSPLIT + split] = s;
        }
        __syncthreads();              // partial stores issued by all threads
        if (t == 0) {
            __threadfence();          // release before arrive
            atomicAdd(&g_cnt[bh], 1);
        }
    } else {
        // -------- WRITER: one CTA per bh, spin then 4x32KB bulk copies -----
        const int bh = blockIdx.x - NREADER;    // 0..31

        if (t == 0) {
            volatile int* p = &g_cnt[bh];
            while (*p < NSPLIT) { __nanosleep(128); }
            __threadfence();                    // acquire
        }
        __syncthreads();

        if (t < D_) {
            const float* __restrict__ pn = g_num + bh * NSPLIT * D_ + t;
            float num = 0.0f, den = 0.0f;
            #pragma unroll
            for (int sp = 0; sp < NSPLIT; sp++) {
                num += __ldcg(pn + sp * D_);
                den += __ldcg(&g_den[bh * NSPLIT + sp]);
            }
            reinterpret_cast<float*>(sm.w.s_w4)[t] = num / den;
        }
        __syncthreads();

        {   // replicate the 256B row into 128 staged rows (8 STS.128 each)
            const float4 v = sm.w.s_w4[t & 15];
            const int r0 = t >> 4;              // 0..15
            #pragma unroll
            for (int i = 0; i < STAGE_ROWS / 16; i++)   // 8 iters
                sm.w.s_buf[(r0 + 16 * i) * (D_ / 4) + (t & 15)] = v;
        }
        __syncthreads();

        if (t == 0) {
            asm volatile("fence.proxy.async.shared::cta;" ::: "memory");
            uint32_t saddr = (uint32_t)__cvta_generic_to_shared(sm.w.s_buf);
            #pragma unroll
            for (int i = 0; i < L_ / STAGE_ROWS; i++) {   // 16 x 32KB = 512KB
                const float* gdst = out + ((size_t)bh * L_
                    + (size_t)i * STAGE_ROWS) * D_;
                asm volatile(
                    "cp.async.bulk.global.shared::cta.bulk_group [%0], [%1], %2;"
                    :: "l"(gdst), "r"(saddr), "r"((int)STAGE_BYTES) : "memory");
            }
            asm volatile("cp.async.bulk.commit_group;" ::: "memory");
            asm volatile("cp.async.bulk.wait_group.read 0;" ::: "memory");

            g_cnt[bh] = 0;    // sole consumer resets for next graph replay
        }
    }
}

extern "C" void kernel_launch(void* const* d_in, const int* in_sizes, int n_in,
                              void* d_out, int out_size)
{
    // metadata order: query, key, value. Query is mathematically irrelevant.
    const float* K = (const float*)d_in[1];
    const float* V = (const float*)d_in[2];
    float* out = (float*)d_out;

    fused_kernel<<<NCTA, 256>>>(K, V, out);
}